// round 6
// baseline (speedup 1.0000x reference)
#include <cuda_runtime.h>
#include <cstdint>

#define NB   256   // batch
#define NL   200   // seq len
#define ND   256   // model dim
#define NH   16    // heads
#define NDH  16    // head dim

// ---------------- scratch (device globals: alloc-free) ----------------
__device__ float g_q[NB * NH * NL * NDH];    // [B,H,L,Dh]
__device__ float g_k[NB * NH * NL * NDH];
__device__ float g_v[NB * NH * NL * NDH];
__device__ float g_ctx[NB * NL * ND];        // [B,L,D]
__device__ float g_u[ND];                    // Wo @ query^T

// ---------------- Kernel 1: fused QKV projection (SGEMM 128x128x8) ----------------
// C[51200, 768] = A[51200,256] @ [Wq|Wk|Wv], + bias, scattered into [B,H,L,Dh].
__global__ __launch_bounds__(256, 2)
void qkv_gemm_kernel(const float* __restrict__ A,
                     const float* __restrict__ Wq, const float* __restrict__ bq,
                     const float* __restrict__ Wk, const float* __restrict__ bk,
                     const float* __restrict__ Wv, const float* __restrict__ bvec)
{
    __shared__ float As[8][128];   // transposed A tile
    __shared__ float Bs[8][128];

    const int tid = threadIdx.x;
    const int bx  = blockIdx.x;        // 0..5  -> which 128-col slab of [Q|K|V]
    const int by  = blockIdx.y;        // 0..399 -> 128-row slab of M=51200

    const int mat   = bx >> 1;         // 0=Q,1=K,2=V
    const int ncol0 = (bx & 1) * 128;  // column offset inside the 256-wide W

    const float* __restrict__ W    = (mat == 0) ? Wq : (mat == 1 ? Wk : Wv);
    const float* __restrict__ bias = (mat == 0) ? bq : (mat == 1 ? bk : bvec);
    float* OUT = (mat == 0) ? g_q : (mat == 1 ? g_k : g_v);

    // global-load assignments
    const int arow = tid >> 1;           // 0..127
    const int acol = (tid & 1) << 2;     // 0 or 4
    const int brow = tid >> 5;           // 0..7
    const int bcol = (tid & 31) << 2;    // 0..124

    const float* Ag = A + (size_t)(by * 128 + arow) * ND + acol;
    const float* Bg = W + (size_t)brow * ND + ncol0 + bcol;

    const int ty = tid >> 4;   // 0..15
    const int tx = tid & 15;   // 0..15

    float acc[8][8];
    #pragma unroll
    for (int i = 0; i < 8; ++i)
        #pragma unroll
        for (int j = 0; j < 8; ++j) acc[i][j] = 0.f;

    for (int k0 = 0; k0 < ND; k0 += 8) {
        float4 av = *(const float4*)(Ag + k0);
        float4 bw = *(const float4*)(Bg + (size_t)k0 * ND);
        __syncthreads();
        As[acol + 0][arow] = av.x;
        As[acol + 1][arow] = av.y;
        As[acol + 2][arow] = av.z;
        As[acol + 3][arow] = av.w;
        *(float4*)&Bs[brow][bcol] = bw;
        __syncthreads();
        #pragma unroll
        for (int kk = 0; kk < 8; ++kk) {
            float a[8], bb[8];
            *(float4*)&a[0]  = *(const float4*)&As[kk][ty * 8];
            *(float4*)&a[4]  = *(const float4*)&As[kk][ty * 8 + 4];
            *(float4*)&bb[0] = *(const float4*)&Bs[kk][tx * 8];
            *(float4*)&bb[4] = *(const float4*)&Bs[kk][tx * 8 + 4];
            #pragma unroll
            for (int i = 0; i < 8; ++i)
                #pragma unroll
                for (int j = 0; j < 8; ++j)
                    acc[i][j] = fmaf(a[i], bb[j], acc[i][j]);
        }
    }

    // epilogue: +bias, scatter to [B,H,L,Dh]
    float bi[8];
    #pragma unroll
    for (int j = 0; j < 8; ++j) bi[j] = bias[ncol0 + tx * 8 + j];

    const int hcol = (ncol0 >> 4) + (tx >> 1);   // head is constant per thread
    const int d0   = (tx & 1) << 3;              // 0 or 8

    #pragma unroll
    for (int i = 0; i < 8; ++i) {
        int mrow = by * 128 + ty * 8 + i;
        int bbat = mrow / NL;
        int ll   = mrow - bbat * NL;
        float* dst = OUT + (((size_t)(bbat * NH + hcol) * NL + ll) << 4) + d0;
        float4 o0 = make_float4(acc[i][0] + bi[0], acc[i][1] + bi[1],
                                acc[i][2] + bi[2], acc[i][3] + bi[3]);
        float4 o1 = make_float4(acc[i][4] + bi[4], acc[i][5] + bi[5],
                                acc[i][6] + bi[6], acc[i][7] + bi[7]);
        *(float4*)dst       = o0;
        *(float4*)(dst + 4) = o1;
    }
}

// ---------------- Kernel 2: fused MHA per (b,h), online softmax ----------------
__global__ __launch_bounds__(256)
void attn_kernel(const int* __restrict__ his_mask)
{
    const int h = blockIdx.x;
    const int b = blockIdx.y;
    const int tid = threadIdx.x;

    __shared__ float Ks[NL * NDH];   // 12.8 KB
    __shared__ float Vs[NL * NDH];   // 12.8 KB
    __shared__ float am[NL];

    const size_t base = (size_t)(b * NH + h) * NL * NDH;
    const float4* k4 = (const float4*)(g_k + base);
    const float4* v4 = (const float4*)(g_v + base);
    float4* Ks4 = (float4*)Ks;
    float4* Vs4 = (float4*)Vs;
    for (int i = tid; i < NL * NDH / 4; i += 256) { Ks4[i] = k4[i]; Vs4[i] = v4[i]; }
    for (int i = tid; i < NL; i += 256)
        am[i] = (his_mask[b * NL + i] > 0) ? 0.f : -10000.f;
    __syncthreads();

    if (tid < NL) {
        const float4* q4 = (const float4*)(g_q + base + (size_t)tid * NDH);
        float4 q0 = q4[0], q1 = q4[1], q2 = q4[2], q3 = q4[3];

        float m = -3.0e38f, ssum = 0.f;
        float acc[16];
        #pragma unroll
        for (int d = 0; d < 16; ++d) acc[d] = 0.f;

        for (int j = 0; j < NL; ++j) {
            const float4* kj = (const float4*)(Ks + j * NDH);
            float4 k0 = kj[0], k1 = kj[1], k2 = kj[2], k3 = kj[3];
            float s = q0.x * k0.x + q0.y * k0.y + q0.z * k0.z + q0.w * k0.w
                    + q1.x * k1.x + q1.y * k1.y + q1.z * k1.z + q1.w * k1.w
                    + q2.x * k2.x + q2.y * k2.y + q2.z * k2.z + q2.w * k2.w
                    + q3.x * k3.x + q3.y * k3.y + q3.z * k3.z + q3.w * k3.w;
            s = s * 0.25f + am[j];                 // 1/sqrt(16) = 0.25, + additive mask
            float mn = fmaxf(m, s);
            float c  = __expf(m - mn);             // ==1 when no new max; exp(-inf)=0 first iter
            float p  = __expf(s - mn);
            ssum = ssum * c + p;
            const float4* vj = (const float4*)(Vs + j * NDH);
            float4 v0 = vj[0], v1 = vj[1], v2 = vj[2], v3 = vj[3];
            acc[0]  = acc[0]  * c + p * v0.x;  acc[1]  = acc[1]  * c + p * v0.y;
            acc[2]  = acc[2]  * c + p * v0.z;  acc[3]  = acc[3]  * c + p * v0.w;
            acc[4]  = acc[4]  * c + p * v1.x;  acc[5]  = acc[5]  * c + p * v1.y;
            acc[6]  = acc[6]  * c + p * v1.z;  acc[7]  = acc[7]  * c + p * v1.w;
            acc[8]  = acc[8]  * c + p * v2.x;  acc[9]  = acc[9]  * c + p * v2.y;
            acc[10] = acc[10] * c + p * v2.z;  acc[11] = acc[11] * c + p * v2.w;
            acc[12] = acc[12] * c + p * v3.x;  acc[13] = acc[13] * c + p * v3.y;
            acc[14] = acc[14] * c + p * v3.z;  acc[15] = acc[15] * c + p * v3.w;
            m = mn;
        }
        float inv = 1.0f / ssum;
        float4* outp = (float4*)(g_ctx + ((size_t)b * NL + tid) * ND + h * NDH);
        outp[0] = make_float4(acc[0]  * inv, acc[1]  * inv, acc[2]  * inv, acc[3]  * inv);
        outp[1] = make_float4(acc[4]  * inv, acc[5]  * inv, acc[6]  * inv, acc[7]  * inv);
        outp[2] = make_float4(acc[8]  * inv, acc[9]  * inv, acc[10] * inv, acc[11] * inv);
        outp[3] = make_float4(acc[12] * inv, acc[13] * inv, acc[14] * inv, acc[15] * inv);
    }
}

// ---------------- Kernel 3a: u = Wo @ query^T  (tiny) ----------------
__global__ __launch_bounds__(256)
void u_kernel(const float* __restrict__ Wo, const float* __restrict__ query)
{
    __shared__ float qs[ND];
    const int tid = threadIdx.x;
    qs[tid] = query[tid];
    __syncthreads();
    const float* row = Wo + (size_t)tid * ND;
    float a0 = 0.f, a1 = 0.f, a2 = 0.f, a3 = 0.f;
    #pragma unroll 8
    for (int n = 0; n < ND; n += 4) {
        a0 = fmaf(row[n + 0], qs[n + 0], a0);
        a1 = fmaf(row[n + 1], qs[n + 1], a1);
        a2 = fmaf(row[n + 2], qs[n + 2], a2);
        a3 = fmaf(row[n + 3], qs[n + 3], a3);
    }
    g_u[tid] = (a0 + a1) + (a2 + a3);
}

// ---------------- Kernel 3b: masked softmax pooling + projected epilogue ----------
// ps[l] = (ctx[b,l]·u)/sqrt(D) (masked); user_repr[b] = (softmax(ps)·ctx[b]) @ Wo + bo
__global__ __launch_bounds__(256)
void pool_kernel(const float* __restrict__ Wo, const float* __restrict__ bo,
                 const int* __restrict__ his_mask, float* __restrict__ out)
{
    const int b    = blockIdx.x;
    const int tid  = threadIdx.x;
    const int lane = tid & 31;
    const int warp = tid >> 5;

    __shared__ float ps[NL];
    __shared__ float pooled[ND];
    __shared__ float red[8];

    const float* C = g_ctx + (size_t)b * NL * ND;

    float4 ua = ((const float4*)g_u)[lane * 2];
    float4 ub = ((const float4*)g_u)[lane * 2 + 1];

    // logits (warp per row)
    for (int l = warp; l < NL; l += 8) {
        const float4* c4 = (const float4*)(C + (size_t)l * ND);
        float4 xa = c4[lane * 2], xb = c4[lane * 2 + 1];
        float acc = xa.x * ua.x + xa.y * ua.y + xa.z * ua.z + xa.w * ua.w
                  + xb.x * ub.x + xb.y * ub.y + xb.z * ub.z + xb.w * ub.w;
        #pragma unroll
        for (int o = 16; o; o >>= 1) acc += __shfl_xor_sync(0xffffffffu, acc, o);
        if (lane == 0)
            ps[l] = (his_mask[b * NL + l] > 0) ? acc * 0.0625f : -1e9f;  // 1/sqrt(256)
    }
    __syncthreads();

    // softmax over 200 logits
    float v = (tid < NL) ? ps[tid] : -3.0e38f;
    float mx = v;
    #pragma unroll
    for (int o = 16; o; o >>= 1) mx = fmaxf(mx, __shfl_xor_sync(0xffffffffu, mx, o));
    if (lane == 0) red[warp] = mx;
    __syncthreads();
    float bm = red[0];
    #pragma unroll
    for (int i = 1; i < 8; ++i) bm = fmaxf(bm, red[i]);

    float e = (tid < NL) ? __expf(v - bm) : 0.f;
    float sv = e;
    #pragma unroll
    for (int o = 16; o; o >>= 1) sv += __shfl_xor_sync(0xffffffffu, sv, o);
    __syncthreads();                      // all done reading red(max) before reuse
    if (lane == 0) red[warp] = sv;
    if (tid < NL) ps[tid] = e;
    __syncthreads();
    float tot = (red[0] + red[1]) + (red[2] + red[3])
              + (red[4] + red[5]) + (red[6] + red[7]);
    float inv = 1.0f / tot;

    // pooled[d] = sum_l p[l] * ctx[b,l,d]
    {
        float a0 = 0.f, a1 = 0.f, a2 = 0.f, a3 = 0.f;
        const float* Cd = C + tid;
        for (int l = 0; l < NL; l += 4) {
            a0 = fmaf(ps[l + 0], Cd[(size_t)(l + 0) * ND], a0);
            a1 = fmaf(ps[l + 1], Cd[(size_t)(l + 1) * ND], a1);
            a2 = fmaf(ps[l + 2], Cd[(size_t)(l + 2) * ND], a2);
            a3 = fmaf(ps[l + 3], Cd[(size_t)(l + 3) * ND], a3);
        }
        pooled[tid] = ((a0 + a1) + (a2 + a3)) * inv;
    }
    __syncthreads();

    // user_repr[b,n] = pooled · Wo[:,n] + bo[n]
    float o = bo[tid];
    const float* Wn = Wo + tid;
    #pragma unroll 8
    for (int d = 0; d < ND; ++d) o = fmaf(pooled[d], Wn[(size_t)d * ND], o);
    out[(size_t)b * ND + tid] = o;
}

// ---------------- launch ----------------
extern "C" void kernel_launch(void* const* d_in, const int* in_sizes, int n_in,
                              void* d_out, int out_size)
{
    const float* news  = (const float*)d_in[0];
    const int*   hmask = (const int*)  d_in[1];
    const float* Wq    = (const float*)d_in[2];
    const float* bq    = (const float*)d_in[3];
    const float* Wk    = (const float*)d_in[4];
    const float* bk    = (const float*)d_in[5];
    const float* Wv    = (const float*)d_in[6];
    const float* bvv   = (const float*)d_in[7];
    const float* Wo    = (const float*)d_in[8];
    const float* bo    = (const float*)d_in[9];
    const float* query = (const float*)d_in[10];
    float* out = (float*)d_out;

    dim3 gemm_grid(6, (NB * NL) / 128);            // 6 x 400
    qkv_gemm_kernel<<<gemm_grid, 256>>>(news, Wq, bq, Wk, bk, Wv, bvv);

    dim3 attn_grid(NH, NB);                        // 16 x 256
    attn_kernel<<<attn_grid, 256>>>(hmask);

    u_kernel<<<1, 256>>>(Wo, query);

    pool_kernel<<<NB, 256>>>(Wo, bo, hmask, out);
}

// round 7
// speedup vs baseline: 1.3038x; 1.3038x over previous
#include <cuda_runtime.h>
#include <cstdint>

#define NB   256   // batch
#define NL   200   // seq len
#define ND   256   // model dim
#define NH   16    // heads
#define NDH  16    // head dim

// ---------------- scratch (device globals: alloc-free) ----------------
__device__ float g_q[NB * NH * NL * NDH];    // [B,H,L,Dh]
__device__ float g_k[NB * NH * NL * NDH];
__device__ float g_v[NB * NH * NL * NDH];
__device__ float g_ctx[NB * NL * ND];        // [B,L,D]
__device__ float g_u[ND];                    // Wo @ query^T

// ---------------- tf32 mma helpers ----------------
__device__ __forceinline__ uint32_t f2tf32(float x) {
    uint32_t r;
    asm("cvt.rna.tf32.f32 %0, %1;" : "=r"(r) : "f"(x));
    return r;
}

__device__ __forceinline__ void mma_tf32(float* d,
                                         const uint32_t* a,
                                         const uint32_t* b)
{
    asm volatile(
        "mma.sync.aligned.m16n8k8.row.col.f32.tf32.tf32.f32 "
        "{%0,%1,%2,%3}, {%4,%5,%6,%7}, {%8,%9}, {%0,%1,%2,%3};\n"
        : "+f"(d[0]), "+f"(d[1]), "+f"(d[2]), "+f"(d[3])
        : "r"(a[0]), "r"(a[1]), "r"(a[2]), "r"(a[3]),
          "r"(b[0]), "r"(b[1]));
}

// ---------------- Kernel 1: QKV projection via tf32 tensor cores ----------------
// C[51200, 768] = A[51200,256] @ [Wq|Wk|Wv] + bias, scattered into [B,H,L,Dh].
// Block tile 128(M) x 64(N), k-chunk 16, double-buffered smem, 8 warps:
// warp tile 64(M) x 16(N) -> exactly one head per warp (16 output cols).
#define BK 16
#define AS_STRIDE 136   // 128 + 8 pad: A-read bank = (8*c + g) % 32, conflict-free
#define BS_STRIDE 72    // 64 + 8 pad:  B-read bank = (8*c + n) % 32, conflict-free

__global__ __launch_bounds__(256, 2)
void qkv_mma_kernel(const float* __restrict__ A,
                    const float* __restrict__ Wq, const float* __restrict__ bq,
                    const float* __restrict__ Wk, const float* __restrict__ bk,
                    const float* __restrict__ Wv, const float* __restrict__ bvec)
{
    __shared__ float As[2][BK][AS_STRIDE];   // [k][m], 17408 B
    __shared__ float Bs[2][BK][BS_STRIDE];   // [k][n],  9216 B

    const int tid = threadIdx.x;
    const int bx  = blockIdx.x;          // 0..11
    const int by  = blockIdx.y;          // 0..399

    const int mat   = bx >> 2;           // 0=Q,1=K,2=V
    const int ncol0 = (bx & 3) * 64;     // column offset inside the 256-wide W

    const float* __restrict__ W    = (mat == 0) ? Wq : (mat == 1 ? Wk : Wv);
    const float* __restrict__ bias = (mat == 0) ? bq : (mat == 1 ? bk : bvec);
    float* OUT = (mat == 0) ? g_q : (mat == 1 ? g_k : g_v);

    const int lane = tid & 31;
    const int wid  = tid >> 5;
    const int warp_m = (wid & 1) * 64;   // 0 or 64
    const int warp_n = (wid >> 1) * 16;  // 0,16,32,48
    const int g = lane >> 2;             // groupID (row within 8)
    const int c = lane & 3;              // k quarter

    // global loaders
    const int am = tid & 127;            // A row within tile
    const int ak = (tid >> 7) * 8;       // k sub-offset 0 or 8
    const float* Aptr = A + (size_t)(by * 128 + am) * ND + ak;

    const int bkr = tid >> 4;            // 0..15 (k row)
    const int bn4 = (tid & 15) * 4;      // n offset
    const float* Bptr = W + (size_t)bkr * ND + ncol0 + bn4;

    float4 pa0, pa1, pb;
    pa0 = *(const float4*)(Aptr);
    pa1 = *(const float4*)(Aptr + 4);
    pb  = *(const float4*)(Bptr);

    // store chunk 0 into buffer 0 (converted to tf32 bits)
    {
        As[0][ak + 0][am] = __uint_as_float(f2tf32(pa0.x));
        As[0][ak + 1][am] = __uint_as_float(f2tf32(pa0.y));
        As[0][ak + 2][am] = __uint_as_float(f2tf32(pa0.z));
        As[0][ak + 3][am] = __uint_as_float(f2tf32(pa0.w));
        As[0][ak + 4][am] = __uint_as_float(f2tf32(pa1.x));
        As[0][ak + 5][am] = __uint_as_float(f2tf32(pa1.y));
        As[0][ak + 6][am] = __uint_as_float(f2tf32(pa1.z));
        As[0][ak + 7][am] = __uint_as_float(f2tf32(pa1.w));
        float4 cv = make_float4(__uint_as_float(f2tf32(pb.x)),
                                __uint_as_float(f2tf32(pb.y)),
                                __uint_as_float(f2tf32(pb.z)),
                                __uint_as_float(f2tf32(pb.w)));
        *(float4*)&Bs[0][bkr][bn4] = cv;
    }
    __syncthreads();

    float acc[4][2][4];
    #pragma unroll
    for (int mi = 0; mi < 4; ++mi)
        #pragma unroll
        for (int nf = 0; nf < 2; ++nf)
            #pragma unroll
            for (int r = 0; r < 4; ++r) acc[mi][nf][r] = 0.f;

    #pragma unroll 1
    for (int ch = 0; ch < ND / BK; ++ch) {
        const int cur = ch & 1;
        if (ch < ND / BK - 1) {
            pa0 = *(const float4*)(Aptr + (ch + 1) * BK);
            pa1 = *(const float4*)(Aptr + (ch + 1) * BK + 4);
            pb  = *(const float4*)(Bptr + (size_t)(ch + 1) * BK * ND);
        }

        #pragma unroll
        for (int ks = 0; ks < 2; ++ks) {
            const int k0 = ks * 8;
            uint32_t afr[4][4];
            uint32_t bfr[2][2];
            #pragma unroll
            for (int mi = 0; mi < 4; ++mi) {
                const int m = warp_m + mi * 16 + g;
                afr[mi][0] = __float_as_uint(As[cur][k0 + c    ][m    ]);
                afr[mi][1] = __float_as_uint(As[cur][k0 + c    ][m + 8]);
                afr[mi][2] = __float_as_uint(As[cur][k0 + c + 4][m    ]);
                afr[mi][3] = __float_as_uint(As[cur][k0 + c + 4][m + 8]);
            }
            #pragma unroll
            for (int nf = 0; nf < 2; ++nf) {
                const int n = warp_n + nf * 8 + g;
                bfr[nf][0] = __float_as_uint(Bs[cur][k0 + c    ][n]);
                bfr[nf][1] = __float_as_uint(Bs[cur][k0 + c + 4][n]);
            }
            #pragma unroll
            for (int mi = 0; mi < 4; ++mi)
                #pragma unroll
                for (int nf = 0; nf < 2; ++nf)
                    mma_tf32(acc[mi][nf], afr[mi], bfr[nf]);
        }

        if (ch < ND / BK - 1) {
            const int nxt = cur ^ 1;
            As[nxt][ak + 0][am] = __uint_as_float(f2tf32(pa0.x));
            As[nxt][ak + 1][am] = __uint_as_float(f2tf32(pa0.y));
            As[nxt][ak + 2][am] = __uint_as_float(f2tf32(pa0.z));
            As[nxt][ak + 3][am] = __uint_as_float(f2tf32(pa0.w));
            As[nxt][ak + 4][am] = __uint_as_float(f2tf32(pa1.x));
            As[nxt][ak + 5][am] = __uint_as_float(f2tf32(pa1.y));
            As[nxt][ak + 6][am] = __uint_as_float(f2tf32(pa1.z));
            As[nxt][ak + 7][am] = __uint_as_float(f2tf32(pa1.w));
            float4 cv = make_float4(__uint_as_float(f2tf32(pb.x)),
                                    __uint_as_float(f2tf32(pb.y)),
                                    __uint_as_float(f2tf32(pb.z)),
                                    __uint_as_float(f2tf32(pb.w)));
            *(float4*)&Bs[nxt][bkr][bn4] = cv;
            __syncthreads();
        }
    }

    // epilogue: +bias, scatter to [B,H,L,Dh]. Each warp owns exactly one head.
    const int h = (ncol0 >> 4) + (wid >> 1);
    #pragma unroll
    for (int mi = 0; mi < 4; ++mi) {
        const int r0 = by * 128 + warp_m + mi * 16 + g;
        const int r1 = r0 + 8;
        const int b0 = r0 / NL, l0 = r0 - b0 * NL;
        const int b1 = r1 / NL, l1 = r1 - b1 * NL;
        float* p0 = OUT + (((size_t)(b0 * NH + h) * NL + l0) << 4);
        float* p1 = OUT + (((size_t)(b1 * NH + h) * NL + l1) << 4);
        #pragma unroll
        for (int nf = 0; nf < 2; ++nf) {
            const int d = nf * 8 + 2 * c;
            const float bi0 = bias[ncol0 + warp_n + d];
            const float bi1 = bias[ncol0 + warp_n + d + 1];
            float2 v0 = make_float2(acc[mi][nf][0] + bi0, acc[mi][nf][1] + bi1);
            float2 v1 = make_float2(acc[mi][nf][2] + bi0, acc[mi][nf][3] + bi1);
            *(float2*)(p0 + d) = v0;
            *(float2*)(p1 + d) = v1;
        }
    }
}

// ---------------- Kernel 2: fused MHA per (b,h) ----------------
// Scores are bounded (|q.k|/4 << 80) so exp() needs no max subtraction:
// masked scores are ~ -10000 -> expf underflows to exact 0.
__global__ __launch_bounds__(224)
void attn_kernel(const int* __restrict__ his_mask)
{
    const int h = blockIdx.x;
    const int b = blockIdx.y;
    const int tid = threadIdx.x;

    __shared__ float Ks[NL * NDH];   // 12.8 KB
    __shared__ float Vs[NL * NDH];   // 12.8 KB
    __shared__ float am[NL];

    const size_t base = (size_t)(b * NH + h) * NL * NDH;
    const float4* k4 = (const float4*)(g_k + base);
    const float4* v4 = (const float4*)(g_v + base);
    float4* Ks4 = (float4*)Ks;
    float4* Vs4 = (float4*)Vs;
    for (int i = tid; i < NL * NDH / 4; i += 224) { Ks4[i] = k4[i]; Vs4[i] = v4[i]; }
    for (int i = tid; i < NL; i += 224)
        am[i] = (his_mask[b * NL + i] > 0) ? 0.f : -10000.f;
    __syncthreads();

    if (tid < NL) {
        const float4* q4 = (const float4*)(g_q + base + (size_t)tid * NDH);
        float4 q0 = q4[0], q1 = q4[1], q2 = q4[2], q3 = q4[3];

        float ssum = 0.f;
        float acc[16];
        #pragma unroll
        for (int d = 0; d < 16; ++d) acc[d] = 0.f;

        for (int j = 0; j < NL; ++j) {
            const float4* kj = (const float4*)(Ks + j * NDH);
            float4 k0 = kj[0], k1 = kj[1], k2 = kj[2], k3 = kj[3];
            float s = q0.x * k0.x + q0.y * k0.y + q0.z * k0.z + q0.w * k0.w
                    + q1.x * k1.x + q1.y * k1.y + q1.z * k1.z + q1.w * k1.w
                    + q2.x * k2.x + q2.y * k2.y + q2.z * k2.z + q2.w * k2.w
                    + q3.x * k3.x + q3.y * k3.y + q3.z * k3.z + q3.w * k3.w;
            float p = __expf(fmaf(s, 0.25f, am[j]));   // 1/sqrt(16)=0.25 + mask
            ssum += p;
            const float4* vj = (const float4*)(Vs + j * NDH);
            float4 v0 = vj[0], v1 = vj[1], v2 = vj[2], v3 = vj[3];
            acc[0]  = fmaf(p, v0.x, acc[0]);   acc[1]  = fmaf(p, v0.y, acc[1]);
            acc[2]  = fmaf(p, v0.z, acc[2]);   acc[3]  = fmaf(p, v0.w, acc[3]);
            acc[4]  = fmaf(p, v1.x, acc[4]);   acc[5]  = fmaf(p, v1.y, acc[5]);
            acc[6]  = fmaf(p, v1.z, acc[6]);   acc[7]  = fmaf(p, v1.w, acc[7]);
            acc[8]  = fmaf(p, v2.x, acc[8]);   acc[9]  = fmaf(p, v2.y, acc[9]);
            acc[10] = fmaf(p, v2.z, acc[10]);  acc[11] = fmaf(p, v2.w, acc[11]);
            acc[12] = fmaf(p, v3.x, acc[12]);  acc[13] = fmaf(p, v3.y, acc[13]);
            acc[14] = fmaf(p, v3.z, acc[14]);  acc[15] = fmaf(p, v3.w, acc[15]);
        }
        float inv = 1.0f / ssum;
        float4* outp = (float4*)(g_ctx + ((size_t)b * NL + tid) * ND + h * NDH);
        outp[0] = make_float4(acc[0]  * inv, acc[1]  * inv, acc[2]  * inv, acc[3]  * inv);
        outp[1] = make_float4(acc[4]  * inv, acc[5]  * inv, acc[6]  * inv, acc[7]  * inv);
        outp[2] = make_float4(acc[8]  * inv, acc[9]  * inv, acc[10] * inv, acc[11] * inv);
        outp[3] = make_float4(acc[12] * inv, acc[13] * inv, acc[14] * inv, acc[15] * inv);
    }
}

// ---------------- Kernel 3a: u = Wo @ query^T  (tiny) ----------------
__global__ __launch_bounds__(256)
void u_kernel(const float* __restrict__ Wo, const float* __restrict__ query)
{
    __shared__ float qs[ND];
    const int tid = threadIdx.x;
    qs[tid] = query[tid];
    __syncthreads();
    const float* row = Wo + (size_t)tid * ND;
    float a0 = 0.f, a1 = 0.f, a2 = 0.f, a3 = 0.f;
    #pragma unroll 8
    for (int n = 0; n < ND; n += 4) {
        a0 = fmaf(row[n + 0], qs[n + 0], a0);
        a1 = fmaf(row[n + 1], qs[n + 1], a1);
        a2 = fmaf(row[n + 2], qs[n + 2], a2);
        a3 = fmaf(row[n + 3], qs[n + 3], a3);
    }
    g_u[tid] = (a0 + a1) + (a2 + a3);
}

// ---------------- Kernel 3b: masked softmax pooling + projected epilogue ----------
// ps[l] = (ctx[b,l]·u)/sqrt(D) (masked); user_repr[b] = (softmax(ps)·ctx[b]) @ Wo + bo
__global__ __launch_bounds__(256)
void pool_kernel(const float* __restrict__ Wo, const float* __restrict__ bo,
                 const int* __restrict__ his_mask, float* __restrict__ out)
{
    const int b    = blockIdx.x;
    const int tid  = threadIdx.x;
    const int lane = tid & 31;
    const int warp = tid >> 5;

    __shared__ float ps[NL];
    __shared__ float pooled[ND];
    __shared__ float red[8];

    const float* C = g_ctx + (size_t)b * NL * ND;

    float4 ua = ((const float4*)g_u)[lane * 2];
    float4 ub = ((const float4*)g_u)[lane * 2 + 1];

    // logits (warp per row)
    for (int l = warp; l < NL; l += 8) {
        const float4* c4 = (const float4*)(C + (size_t)l * ND);
        float4 xa = c4[lane * 2], xb = c4[lane * 2 + 1];
        float acc = xa.x * ua.x + xa.y * ua.y + xa.z * ua.z + xa.w * ua.w
                  + xb.x * ub.x + xb.y * ub.y + xb.z * ub.z + xb.w * ub.w;
        #pragma unroll
        for (int o = 16; o; o >>= 1) acc += __shfl_xor_sync(0xffffffffu, acc, o);
        if (lane == 0)
            ps[l] = (his_mask[b * NL + l] > 0) ? acc * 0.0625f : -1e9f;  // 1/sqrt(256)
    }
    __syncthreads();

    // softmax over 200 logits
    float v = (tid < NL) ? ps[tid] : -3.0e38f;
    float mx = v;
    #pragma unroll
    for (int o = 16; o; o >>= 1) mx = fmaxf(mx, __shfl_xor_sync(0xffffffffu, mx, o));
    if (lane == 0) red[warp] = mx;
    __syncthreads();
    float bm = red[0];
    #pragma unroll
    for (int i = 1; i < 8; ++i) bm = fmaxf(bm, red[i]);

    float e = (tid < NL) ? __expf(v - bm) : 0.f;
    float sv = e;
    #pragma unroll
    for (int o = 16; o; o >>= 1) sv += __shfl_xor_sync(0xffffffffu, sv, o);
    __syncthreads();                      // all done reading red(max) before reuse
    if (lane == 0) red[warp] = sv;
    if (tid < NL) ps[tid] = e;
    __syncthreads();
    float tot = (red[0] + red[1]) + (red[2] + red[3])
              + (red[4] + red[5]) + (red[6] + red[7]);
    float inv = 1.0f / tot;

    // pooled[d] = sum_l p[l] * ctx[b,l,d]
    {
        float a0 = 0.f, a1 = 0.f, a2 = 0.f, a3 = 0.f;
        const float* Cd = C + tid;
        for (int l = 0; l < NL; l += 4) {
            a0 = fmaf(ps[l + 0], Cd[(size_t)(l + 0) * ND], a0);
            a1 = fmaf(ps[l + 1], Cd[(size_t)(l + 1) * ND], a1);
            a2 = fmaf(ps[l + 2], Cd[(size_t)(l + 2) * ND], a2);
            a3 = fmaf(ps[l + 3], Cd[(size_t)(l + 3) * ND], a3);
        }
        pooled[tid] = ((a0 + a1) + (a2 + a3)) * inv;
    }
    __syncthreads();

    // user_repr[b,n] = pooled · Wo[:,n] + bo[n]
    float o = bo[tid];
    const float* Wn = Wo + tid;
    #pragma unroll 8
    for (int d = 0; d < ND; ++d) o = fmaf(pooled[d], Wn[(size_t)d * ND], o);
    out[(size_t)b * ND + tid] = o;
}

// ---------------- launch ----------------
extern "C" void kernel_launch(void* const* d_in, const int* in_sizes, int n_in,
                              void* d_out, int out_size)
{
    const float* news  = (const float*)d_in[0];
    const int*   hmask = (const int*)  d_in[1];
    const float* Wq    = (const float*)d_in[2];
    const float* bq    = (const float*)d_in[3];
    const float* Wk    = (const float*)d_in[4];
    const float* bk    = (const float*)d_in[5];
    const float* Wv    = (const float*)d_in[6];
    const float* bvv   = (const float*)d_in[7];
    const float* Wo    = (const float*)d_in[8];
    const float* bo    = (const float*)d_in[9];
    const float* query = (const float*)d_in[10];
    float* out = (float*)d_out;

    dim3 gemm_grid(12, (NB * NL) / 128);           // 12 x 400
    qkv_mma_kernel<<<gemm_grid, 256>>>(news, Wq, bq, Wk, bk, Wv, bvv);

    dim3 attn_grid(NH, NB);                        // 16 x 256
    attn_kernel<<<attn_grid, 224>>>(hmask);

    u_kernel<<<1, 256>>>(Wo, query);

    pool_kernel<<<NB, 256>>>(Wo, bo, hmask, out);
}

// round 10
// speedup vs baseline: 1.8846x; 1.4455x over previous
#include <cuda_runtime.h>
#include <cstdint>

#define NB   256   // batch
#define NL   200   // seq len
#define ND   256   // model dim
#define NH   16    // heads
#define NDH  16    // head dim

// ---------------- scratch (device globals: alloc-free) ----------------
__device__ float g_q[NB * NH * NL * NDH];    // [B,H,L,Dh]
__device__ float g_k[NB * NH * NL * NDH];
__device__ float g_v[NB * NH * NL * NDH];
__device__ float g_ctx[NB * NL * ND];        // [B,L,D]
__device__ float g_u[ND];                    // Wo @ query^T

// ---------------- tf32 mma helpers ----------------
__device__ __forceinline__ uint32_t f2tf32(float x) {
    uint32_t r;
    asm("cvt.rna.tf32.f32 %0, %1;" : "=r"(r) : "f"(x));
    return r;
}

__device__ __forceinline__ void mma_tf32(float* d,
                                         const uint32_t* a,
                                         const uint32_t* b)
{
    asm volatile(
        "mma.sync.aligned.m16n8k8.row.col.f32.tf32.tf32.f32 "
        "{%0,%1,%2,%3}, {%4,%5,%6,%7}, {%8,%9}, {%0,%1,%2,%3};\n"
        : "+f"(d[0]), "+f"(d[1]), "+f"(d[2]), "+f"(d[3])
        : "r"(a[0]), "r"(a[1]), "r"(a[2]), "r"(a[3]),
          "r"(b[0]), "r"(b[1]));
}

// ---------------- Kernel 1: QKV projection via tf32 tensor cores ----------------
// C[51200, 768] = A[51200,256] @ [Wq|Wk|Wv] + bias, scattered into [B,H,L,Dh].
#define BK 16
#define AS_STRIDE 136
#define BS_STRIDE 72

__global__ __launch_bounds__(256, 2)
void qkv_mma_kernel(const float* __restrict__ A,
                    const float* __restrict__ Wq, const float* __restrict__ bq,
                    const float* __restrict__ Wk, const float* __restrict__ bk,
                    const float* __restrict__ Wv, const float* __restrict__ bvec)
{
    __shared__ float As[2][BK][AS_STRIDE];
    __shared__ float Bs[2][BK][BS_STRIDE];

    const int tid = threadIdx.x;
    const int bx  = blockIdx.x;          // 0..11
    const int by  = blockIdx.y;          // 0..399

    const int mat   = bx >> 2;           // 0=Q,1=K,2=V
    const int ncol0 = (bx & 3) * 64;

    const float* __restrict__ W    = (mat == 0) ? Wq : (mat == 1 ? Wk : Wv);
    const float* __restrict__ bias = (mat == 0) ? bq : (mat == 1 ? bk : bvec);
    float* OUT = (mat == 0) ? g_q : (mat == 1 ? g_k : g_v);

    const int lane = tid & 31;
    const int wid  = tid >> 5;
    const int warp_m = (wid & 1) * 64;
    const int warp_n = (wid >> 1) * 16;
    const int g = lane >> 2;
    const int c = lane & 3;

    const int am = tid & 127;
    const int ak = (tid >> 7) * 8;
    const float* Aptr = A + (size_t)(by * 128 + am) * ND + ak;

    const int bkr = tid >> 4;
    const int bn4 = (tid & 15) * 4;
    const float* Bptr = W + (size_t)bkr * ND + ncol0 + bn4;

    float4 pa0, pa1, pb;
    pa0 = *(const float4*)(Aptr);
    pa1 = *(const float4*)(Aptr + 4);
    pb  = *(const float4*)(Bptr);

    {
        As[0][ak + 0][am] = __uint_as_float(f2tf32(pa0.x));
        As[0][ak + 1][am] = __uint_as_float(f2tf32(pa0.y));
        As[0][ak + 2][am] = __uint_as_float(f2tf32(pa0.z));
        As[0][ak + 3][am] = __uint_as_float(f2tf32(pa0.w));
        As[0][ak + 4][am] = __uint_as_float(f2tf32(pa1.x));
        As[0][ak + 5][am] = __uint_as_float(f2tf32(pa1.y));
        As[0][ak + 6][am] = __uint_as_float(f2tf32(pa1.z));
        As[0][ak + 7][am] = __uint_as_float(f2tf32(pa1.w));
        float4 cv = make_float4(__uint_as_float(f2tf32(pb.x)),
                                __uint_as_float(f2tf32(pb.y)),
                                __uint_as_float(f2tf32(pb.z)),
                                __uint_as_float(f2tf32(pb.w)));
        *(float4*)&Bs[0][bkr][bn4] = cv;
    }
    __syncthreads();

    float acc[4][2][4];
    #pragma unroll
    for (int mi = 0; mi < 4; ++mi)
        #pragma unroll
        for (int nf = 0; nf < 2; ++nf)
            #pragma unroll
            for (int r = 0; r < 4; ++r) acc[mi][nf][r] = 0.f;

    #pragma unroll 1
    for (int ch = 0; ch < ND / BK; ++ch) {
        const int cur = ch & 1;
        if (ch < ND / BK - 1) {
            pa0 = *(const float4*)(Aptr + (ch + 1) * BK);
            pa1 = *(const float4*)(Aptr + (ch + 1) * BK + 4);
            pb  = *(const float4*)(Bptr + (size_t)(ch + 1) * BK * ND);
        }

        #pragma unroll
        for (int ks = 0; ks < 2; ++ks) {
            const int k0 = ks * 8;
            uint32_t afr[4][4];
            uint32_t bfr[2][2];
            #pragma unroll
            for (int mi = 0; mi < 4; ++mi) {
                const int m = warp_m + mi * 16 + g;
                afr[mi][0] = __float_as_uint(As[cur][k0 + c    ][m    ]);
                afr[mi][1] = __float_as_uint(As[cur][k0 + c    ][m + 8]);
                afr[mi][2] = __float_as_uint(As[cur][k0 + c + 4][m    ]);
                afr[mi][3] = __float_as_uint(As[cur][k0 + c + 4][m + 8]);
            }
            #pragma unroll
            for (int nf = 0; nf < 2; ++nf) {
                const int n = warp_n + nf * 8 + g;
                bfr[nf][0] = __float_as_uint(Bs[cur][k0 + c    ][n]);
                bfr[nf][1] = __float_as_uint(Bs[cur][k0 + c + 4][n]);
            }
            #pragma unroll
            for (int mi = 0; mi < 4; ++mi)
                #pragma unroll
                for (int nf = 0; nf < 2; ++nf)
                    mma_tf32(acc[mi][nf], afr[mi], bfr[nf]);
        }

        if (ch < ND / BK - 1) {
            const int nxt = cur ^ 1;
            As[nxt][ak + 0][am] = __uint_as_float(f2tf32(pa0.x));
            As[nxt][ak + 1][am] = __uint_as_float(f2tf32(pa0.y));
            As[nxt][ak + 2][am] = __uint_as_float(f2tf32(pa0.z));
            As[nxt][ak + 3][am] = __uint_as_float(f2tf32(pa0.w));
            As[nxt][ak + 4][am] = __uint_as_float(f2tf32(pa1.x));
            As[nxt][ak + 5][am] = __uint_as_float(f2tf32(pa1.y));
            As[nxt][ak + 6][am] = __uint_as_float(f2tf32(pa1.z));
            As[nxt][ak + 7][am] = __uint_as_float(f2tf32(pa1.w));
            float4 cv = make_float4(__uint_as_float(f2tf32(pb.x)),
                                    __uint_as_float(f2tf32(pb.y)),
                                    __uint_as_float(f2tf32(pb.z)),
                                    __uint_as_float(f2tf32(pb.w)));
            *(float4*)&Bs[nxt][bkr][bn4] = cv;
            __syncthreads();
        }
    }

    const int h = (ncol0 >> 4) + (wid >> 1);
    #pragma unroll
    for (int mi = 0; mi < 4; ++mi) {
        const int r0 = by * 128 + warp_m + mi * 16 + g;
        const int r1 = r0 + 8;
        const int b0 = r0 / NL, l0 = r0 - b0 * NL;
        const int b1 = r1 / NL, l1 = r1 - b1 * NL;
        float* p0 = OUT + (((size_t)(b0 * NH + h) * NL + l0) << 4);
        float* p1 = OUT + (((size_t)(b1 * NH + h) * NL + l1) << 4);
        #pragma unroll
        for (int nf = 0; nf < 2; ++nf) {
            const int d = nf * 8 + 2 * c;
            const float bi0 = bias[ncol0 + warp_n + d];
            const float bi1 = bias[ncol0 + warp_n + d + 1];
            float2 v0 = make_float2(acc[mi][nf][0] + bi0, acc[mi][nf][1] + bi1);
            float2 v1 = make_float2(acc[mi][nf][2] + bi0, acc[mi][nf][3] + bi1);
            *(float2*)(p0 + d) = v0;
            *(float2*)(p1 + d) = v1;
        }
    }
}

// ---------------- Kernel 2: tensor-core MHA per (b,h) ----------------
// S = Q K^T via mma (tf32), exp (no max: scores bounded, mask -> exact 0),
// P re-laid C-frag -> A-frag through warp-private smem staging, PV via mma.
#define VT_STRIDE 212
#define QK_STRIDE 17
#define PST_STRIDE 10   // EVEN stride: row base stays 8B-aligned for the float2 store

__global__ __launch_bounds__(256)
void attn_kernel(const int* __restrict__ his_mask)
{
    const int h = blockIdx.x;
    const int b = blockIdx.y;
    const int tid  = threadIdx.x;
    const int lane = tid & 31;
    const int wid  = tid >> 5;
    const int g = lane >> 2;     // row within 8
    const int c = lane & 3;      // quad col

    __shared__ float Qs[208][QK_STRIDE];        // tf32 bits, rows 200..207 zeroed
    __shared__ float Ks[200][QK_STRIDE];        // tf32 bits
    __shared__ float Vt[16][VT_STRIDE];         // transposed V, tf32 bits
    __shared__ float am[NL];
    __shared__ float Pst[8][16][PST_STRIDE];    // per-warp P staging (8B-aligned rows)

    const size_t base = (size_t)(b * NH + h) * NL * NDH;

    // loaders: 200 rows x 16, in float4 chunks
    for (int i = tid; i < NL * 4; i += 256) {
        const int row = i >> 2;
        const int d4  = (i & 3) << 2;
        float4 q = *(const float4*)(g_q + base + row * NDH + d4);
        float4 k = *(const float4*)(g_k + base + row * NDH + d4);
        float4 v = *(const float4*)(g_v + base + row * NDH + d4);
        Qs[row][d4 + 0] = __uint_as_float(f2tf32(q.x));
        Qs[row][d4 + 1] = __uint_as_float(f2tf32(q.y));
        Qs[row][d4 + 2] = __uint_as_float(f2tf32(q.z));
        Qs[row][d4 + 3] = __uint_as_float(f2tf32(q.w));
        Ks[row][d4 + 0] = __uint_as_float(f2tf32(k.x));
        Ks[row][d4 + 1] = __uint_as_float(f2tf32(k.y));
        Ks[row][d4 + 2] = __uint_as_float(f2tf32(k.z));
        Ks[row][d4 + 3] = __uint_as_float(f2tf32(k.w));
        Vt[d4 + 0][row] = __uint_as_float(f2tf32(v.x));
        Vt[d4 + 1][row] = __uint_as_float(f2tf32(v.y));
        Vt[d4 + 2][row] = __uint_as_float(f2tf32(v.z));
        Vt[d4 + 3][row] = __uint_as_float(f2tf32(v.w));
    }
    // zero Q pad rows (200..207)
    for (int i = tid; i < 8 * 16; i += 256)
        Qs[200 + (i >> 4)][i & 15] = 0.f;
    for (int i = tid; i < NL; i += 256)
        am[i] = (his_mask[b * NL + i] > 0) ? 0.f : -10000.f;
    __syncthreads();

    // 13 row-tiles of 16, round-robin over 8 warps
    for (int t = wid; t < 13; t += 8) {
        const int r0 = t * 16;

        // Q a-frags (persistent over key loop): 2 k-steps
        uint32_t aq[2][4];
        #pragma unroll
        for (int ks = 0; ks < 2; ++ks) {
            const int kk = ks * 8;
            aq[ks][0] = __float_as_uint(Qs[r0 + g    ][c     + kk]);
            aq[ks][1] = __float_as_uint(Qs[r0 + g + 8][c     + kk]);
            aq[ks][2] = __float_as_uint(Qs[r0 + g    ][c + 4 + kk]);
            aq[ks][3] = __float_as_uint(Qs[r0 + g + 8][c + 4 + kk]);
        }

        float ctx0[4] = {0.f, 0.f, 0.f, 0.f};   // dh 0..7
        float ctx1[4] = {0.f, 0.f, 0.f, 0.f};   // dh 8..15
        float sum_lo = 0.f, sum_hi = 0.f;

        #pragma unroll 1
        for (int kc = 0; kc < NL / 8; ++kc) {
            const int k0 = kc * 8;

            // K b-frags: b0 = K[k0+g][c + 8ks], b1 = K[k0+g][c+4+8ks]
            uint32_t bk0[2], bk1[2];
            bk0[0] = __float_as_uint(Ks[k0 + g][c     ]);
            bk0[1] = __float_as_uint(Ks[k0 + g][c + 4 ]);
            bk1[0] = __float_as_uint(Ks[k0 + g][c + 8 ]);
            bk1[1] = __float_as_uint(Ks[k0 + g][c + 12]);

            float s[4] = {0.f, 0.f, 0.f, 0.f};
            mma_tf32(s, aq[0], bk0);
            mma_tf32(s, aq[1], bk1);

            const float a0 = am[k0 + 2 * c];
            const float a1 = am[k0 + 2 * c + 1];
            float p0 = __expf(fmaf(s[0], 0.25f, a0));
            float p1 = __expf(fmaf(s[1], 0.25f, a1));
            float p2 = __expf(fmaf(s[2], 0.25f, a0));
            float p3 = __expf(fmaf(s[3], 0.25f, a1));

            // round P to tf32 ONCE; use same values for numerator and denominator
            const uint32_t t0 = f2tf32(p0), t1 = f2tf32(p1);
            const uint32_t t2 = f2tf32(p2), t3 = f2tf32(p3);
            const float q0 = __uint_as_float(t0), q1 = __uint_as_float(t1);
            const float q2 = __uint_as_float(t2), q3 = __uint_as_float(t3);
            sum_lo += q0 + q1;
            sum_hi += q2 + q3;

            // stage C-frag -> A-frag layout (rows are 40B apart: float2 stays aligned)
            *(float2*)&Pst[wid][g    ][2 * c] = make_float2(q0, q1);
            *(float2*)&Pst[wid][g + 8][2 * c] = make_float2(q2, q3);
            __syncwarp();

            uint32_t ap[4];
            ap[0] = __float_as_uint(Pst[wid][g    ][c    ]);
            ap[1] = __float_as_uint(Pst[wid][g + 8][c    ]);
            ap[2] = __float_as_uint(Pst[wid][g    ][c + 4]);
            ap[3] = __float_as_uint(Pst[wid][g + 8][c + 4]);

            uint32_t bv0[2], bv1[2];
            bv0[0] = __float_as_uint(Vt[g    ][k0 + c    ]);
            bv0[1] = __float_as_uint(Vt[g    ][k0 + c + 4]);
            bv1[0] = __float_as_uint(Vt[g + 8][k0 + c    ]);
            bv1[1] = __float_as_uint(Vt[g + 8][k0 + c + 4]);

            mma_tf32(ctx0, ap, bv0);
            mma_tf32(ctx1, ap, bv1);
            __syncwarp();
        }

        // row sums: reduce across the 4 quad threads
        sum_lo += __shfl_xor_sync(0xffffffffu, sum_lo, 1);
        sum_lo += __shfl_xor_sync(0xffffffffu, sum_lo, 2);
        sum_hi += __shfl_xor_sync(0xffffffffu, sum_hi, 1);
        sum_hi += __shfl_xor_sync(0xffffffffu, sum_hi, 2);
        const float inv_lo = 1.0f / sum_lo;
        const float inv_hi = 1.0f / sum_hi;

        const int row_lo = r0 + g;
        const int row_hi = r0 + g + 8;
        if (row_lo < NL) {
            float* p = g_ctx + ((size_t)b * NL + row_lo) * ND + h * NDH;
            *(float2*)(p + 2 * c)     = make_float2(ctx0[0] * inv_lo, ctx0[1] * inv_lo);
            *(float2*)(p + 8 + 2 * c) = make_float2(ctx1[0] * inv_lo, ctx1[1] * inv_lo);
        }
        if (row_hi < NL) {
            float* p = g_ctx + ((size_t)b * NL + row_hi) * ND + h * NDH;
            *(float2*)(p + 2 * c)     = make_float2(ctx0[2] * inv_hi, ctx0[3] * inv_hi);
            *(float2*)(p + 8 + 2 * c) = make_float2(ctx1[2] * inv_hi, ctx1[3] * inv_hi);
        }
    }
}

// ---------------- Kernel 3a: u = Wo @ query^T  (tiny) ----------------
__global__ __launch_bounds__(256)
void u_kernel(const float* __restrict__ Wo, const float* __restrict__ query)
{
    __shared__ float qs[ND];
    const int tid = threadIdx.x;
    qs[tid] = query[tid];
    __syncthreads();
    const float* row = Wo + (size_t)tid * ND;
    float a0 = 0.f, a1 = 0.f, a2 = 0.f, a3 = 0.f;
    #pragma unroll 8
    for (int n = 0; n < ND; n += 4) {
        a0 = fmaf(row[n + 0], qs[n + 0], a0);
        a1 = fmaf(row[n + 1], qs[n + 1], a1);
        a2 = fmaf(row[n + 2], qs[n + 2], a2);
        a3 = fmaf(row[n + 3], qs[n + 3], a3);
    }
    g_u[tid] = (a0 + a1) + (a2 + a3);
}

// ---------------- Kernel 3b: masked softmax pooling + projected epilogue ----------
__global__ __launch_bounds__(256)
void pool_kernel(const float* __restrict__ Wo, const float* __restrict__ bo,
                 const int* __restrict__ his_mask, float* __restrict__ out)
{
    const int b    = blockIdx.x;
    const int tid  = threadIdx.x;
    const int lane = tid & 31;
    const int warp = tid >> 5;

    __shared__ float ps[NL];
    __shared__ float pooled[ND];
    __shared__ float red[8];

    const float* C = g_ctx + (size_t)b * NL * ND;

    float4 ua = ((const float4*)g_u)[lane * 2];
    float4 ub = ((const float4*)g_u)[lane * 2 + 1];

    for (int l = warp; l < NL; l += 8) {
        const float4* c4 = (const float4*)(C + (size_t)l * ND);
        float4 xa = c4[lane * 2], xb = c4[lane * 2 + 1];
        float acc = xa.x * ua.x + xa.y * ua.y + xa.z * ua.z + xa.w * ua.w
                  + xb.x * ub.x + xb.y * ub.y + xb.z * ub.z + xb.w * ub.w;
        #pragma unroll
        for (int o = 16; o; o >>= 1) acc += __shfl_xor_sync(0xffffffffu, acc, o);
        if (lane == 0)
            ps[l] = (his_mask[b * NL + l] > 0) ? acc * 0.0625f : -1e9f;
    }
    __syncthreads();

    float v = (tid < NL) ? ps[tid] : -3.0e38f;
    float mx = v;
    #pragma unroll
    for (int o = 16; o; o >>= 1) mx = fmaxf(mx, __shfl_xor_sync(0xffffffffu, mx, o));
    if (lane == 0) red[warp] = mx;
    __syncthreads();
    float bm = red[0];
    #pragma unroll
    for (int i = 1; i < 8; ++i) bm = fmaxf(bm, red[i]);

    float e = (tid < NL) ? __expf(v - bm) : 0.f;
    float sv = e;
    #pragma unroll
    for (int o = 16; o; o >>= 1) sv += __shfl_xor_sync(0xffffffffu, sv, o);
    __syncthreads();
    if (lane == 0) red[warp] = sv;
    if (tid < NL) ps[tid] = e;
    __syncthreads();
    float tot = (red[0] + red[1]) + (red[2] + red[3])
              + (red[4] + red[5]) + (red[6] + red[7]);
    float inv = 1.0f / tot;

    {
        float a0 = 0.f, a1 = 0.f, a2 = 0.f, a3 = 0.f;
        const float* Cd = C + tid;
        for (int l = 0; l < NL; l += 4) {
            a0 = fmaf(ps[l + 0], Cd[(size_t)(l + 0) * ND], a0);
            a1 = fmaf(ps[l + 1], Cd[(size_t)(l + 1) * ND], a1);
            a2 = fmaf(ps[l + 2], Cd[(size_t)(l + 2) * ND], a2);
            a3 = fmaf(ps[l + 3], Cd[(size_t)(l + 3) * ND], a3);
        }
        pooled[tid] = ((a0 + a1) + (a2 + a3)) * inv;
    }
    __syncthreads();

    float o = bo[tid];
    const float* Wn = Wo + tid;
    #pragma unroll 8
    for (int d = 0; d < ND; ++d) o = fmaf(pooled[d], Wn[(size_t)d * ND], o);
    out[(size_t)b * ND + tid] = o;
}

// ---------------- launch ----------------
extern "C" void kernel_launch(void* const* d_in, const int* in_sizes, int n_in,
                              void* d_out, int out_size)
{
    const float* news  = (const float*)d_in[0];
    const int*   hmask = (const int*)  d_in[1];
    const float* Wq    = (const float*)d_in[2];
    const float* bq    = (const float*)d_in[3];
    const float* Wk    = (const float*)d_in[4];
    const float* bk    = (const float*)d_in[5];
    const float* Wv    = (const float*)d_in[6];
    const float* bvv   = (const float*)d_in[7];
    const float* Wo    = (const float*)d_in[8];
    const float* bo    = (const float*)d_in[9];
    const float* query = (const float*)d_in[10];
    float* out = (float*)d_out;

    dim3 gemm_grid(12, (NB * NL) / 128);           // 12 x 400
    qkv_mma_kernel<<<gemm_grid, 256>>>(news, Wq, bq, Wk, bk, Wv, bvv);

    dim3 attn_grid(NH, NB);                        // 16 x 256
    attn_kernel<<<attn_grid, 256>>>(hmask);

    u_kernel<<<1, 256>>>(Wo, query);

    pool_kernel<<<NB, 256>>>(Wo, bo, hmask, out);
}

// round 11
// speedup vs baseline: 2.1957x; 1.1651x over previous
#include <cuda_runtime.h>
#include <cstdint>

#define NB   256   // batch
#define NL   200   // seq len
#define ND   256   // model dim
#define NH   16    // heads
#define NDH  16    // head dim

// ---------------- scratch (device globals: alloc-free) ----------------
__device__ float g_q[NB * NH * NL * NDH];    // [B,H,L,Dh]
__device__ float g_k[NB * NH * NL * NDH];
__device__ float g_v[NB * NH * NL * NDH];
__device__ float g_ctx[NB * NL * ND];        // [B,L,D]
__device__ float g_u[ND];                    // Wo @ query^T

// ---------------- tf32 mma helpers ----------------
__device__ __forceinline__ uint32_t f2tf32(float x) {
    uint32_t r;
    asm("cvt.rna.tf32.f32 %0, %1;" : "=r"(r) : "f"(x));
    return r;
}

__device__ __forceinline__ void mma_tf32(float* d,
                                         const uint32_t* a,
                                         const uint32_t* b)
{
    asm volatile(
        "mma.sync.aligned.m16n8k8.row.col.f32.tf32.tf32.f32 "
        "{%0,%1,%2,%3}, {%4,%5,%6,%7}, {%8,%9}, {%0,%1,%2,%3};\n"
        : "+f"(d[0]), "+f"(d[1]), "+f"(d[2]), "+f"(d[3])
        : "r"(a[0]), "r"(a[1]), "r"(a[2]), "r"(a[3]),
          "r"(b[0]), "r"(b[1]));
}

// ---------------- Kernel 1: QKV projection via tf32 tensor cores ----------------
// C[51200, 768] = A[51200,256] @ [Wq|Wk|Wv] + bias, scattered into [B,H,L,Dh].
// Block tile 128(M) x 128(N), k-chunk 16, double-buffered, 8 warps (2M x 4N),
// warp tile 64x32 -> 1.5 LDS per MMA.
#define BK 16
#define ST 136   // smem stride for As & Bs: 136 % 32 == 8 -> frag banks (8c+g), conflict-free

__global__ __launch_bounds__(256)
void qkv_mma_kernel(const float* __restrict__ A,
                    const float* __restrict__ Wq, const float* __restrict__ bq,
                    const float* __restrict__ Wk, const float* __restrict__ bk,
                    const float* __restrict__ Wv, const float* __restrict__ bvec)
{
    __shared__ float As[2][BK][ST];   // transposed A tile [k][m], m<128
    __shared__ float Bs[2][BK][ST];   // B tile [k][n], n<128

    const int tid = threadIdx.x;
    const int bx  = blockIdx.x;          // 0..5 : N-slab of 128 within [Q|K|V]
    const int by  = blockIdx.y;          // 0..399

    const int mat   = bx >> 1;           // 0=Q,1=K,2=V
    const int ncol0 = (bx & 1) * 128;    // 0 or 128 inside the 256-wide W

    const float* __restrict__ W    = (mat == 0) ? Wq : (mat == 1 ? Wk : Wv);
    const float* __restrict__ bias = (mat == 0) ? bq : (mat == 1 ? bk : bvec);
    float* OUT = (mat == 0) ? g_q : (mat == 1 ? g_k : g_v);

    const int lane = tid & 31;
    const int wid  = tid >> 5;
    const int warp_m = (wid & 1) * 64;   // 0 or 64
    const int warp_n = (wid >> 1) * 32;  // 0,32,64,96
    const int g = lane >> 2;             // row within 8
    const int c = lane & 3;              // k quarter

    // A loader: 128 rows x 16 k -> 8 elems/thread (2 float4), stored transposed
    const int am = tid & 127;
    const int ak = (tid >> 7) * 8;       // 0 or 8
    const float* Aptr = A + (size_t)(by * 128 + am) * ND + ak;

    // B loader: 16 k-rows x 128 n -> 8 elems/thread (2 float4), stored row-major
    const int bkr = tid >> 4;            // 0..15
    const int bn8 = (tid & 15) * 8;      // 0..120
    const float* Bptr = W + (size_t)bkr * ND + ncol0 + bn8;

    float4 pa0, pa1, pb0, pb1;
    pa0 = *(const float4*)(Aptr);
    pa1 = *(const float4*)(Aptr + 4);
    pb0 = *(const float4*)(Bptr);
    pb1 = *(const float4*)(Bptr + 4);

    {
        As[0][ak + 0][am] = __uint_as_float(f2tf32(pa0.x));
        As[0][ak + 1][am] = __uint_as_float(f2tf32(pa0.y));
        As[0][ak + 2][am] = __uint_as_float(f2tf32(pa0.z));
        As[0][ak + 3][am] = __uint_as_float(f2tf32(pa0.w));
        As[0][ak + 4][am] = __uint_as_float(f2tf32(pa1.x));
        As[0][ak + 5][am] = __uint_as_float(f2tf32(pa1.y));
        As[0][ak + 6][am] = __uint_as_float(f2tf32(pa1.z));
        As[0][ak + 7][am] = __uint_as_float(f2tf32(pa1.w));
        float4 cb0 = make_float4(__uint_as_float(f2tf32(pb0.x)),
                                 __uint_as_float(f2tf32(pb0.y)),
                                 __uint_as_float(f2tf32(pb0.z)),
                                 __uint_as_float(f2tf32(pb0.w)));
        float4 cb1 = make_float4(__uint_as_float(f2tf32(pb1.x)),
                                 __uint_as_float(f2tf32(pb1.y)),
                                 __uint_as_float(f2tf32(pb1.z)),
                                 __uint_as_float(f2tf32(pb1.w)));
        *(float4*)&Bs[0][bkr][bn8]     = cb0;
        *(float4*)&Bs[0][bkr][bn8 + 4] = cb1;
    }
    __syncthreads();

    float acc[4][4][4];
    #pragma unroll
    for (int mi = 0; mi < 4; ++mi)
        #pragma unroll
        for (int nf = 0; nf < 4; ++nf)
            #pragma unroll
            for (int r = 0; r < 4; ++r) acc[mi][nf][r] = 0.f;

    #pragma unroll 1
    for (int ch = 0; ch < ND / BK; ++ch) {
        const int cur = ch & 1;
        if (ch < ND / BK - 1) {
            pa0 = *(const float4*)(Aptr + (ch + 1) * BK);
            pa1 = *(const float4*)(Aptr + (ch + 1) * BK + 4);
            pb0 = *(const float4*)(Bptr + (size_t)(ch + 1) * BK * ND);
            pb1 = *(const float4*)(Bptr + (size_t)(ch + 1) * BK * ND + 4);
        }

        #pragma unroll
        for (int ks = 0; ks < 2; ++ks) {
            const int k0 = ks * 8;
            uint32_t afr[4][4];
            uint32_t bfr[4][2];
            #pragma unroll
            for (int mi = 0; mi < 4; ++mi) {
                const int m = warp_m + mi * 16 + g;
                afr[mi][0] = __float_as_uint(As[cur][k0 + c    ][m    ]);
                afr[mi][1] = __float_as_uint(As[cur][k0 + c    ][m + 8]);
                afr[mi][2] = __float_as_uint(As[cur][k0 + c + 4][m    ]);
                afr[mi][3] = __float_as_uint(As[cur][k0 + c + 4][m + 8]);
            }
            #pragma unroll
            for (int nf = 0; nf < 4; ++nf) {
                const int n = warp_n + nf * 8 + g;
                bfr[nf][0] = __float_as_uint(Bs[cur][k0 + c    ][n]);
                bfr[nf][1] = __float_as_uint(Bs[cur][k0 + c + 4][n]);
            }
            #pragma unroll
            for (int mi = 0; mi < 4; ++mi)
                #pragma unroll
                for (int nf = 0; nf < 4; ++nf)
                    mma_tf32(acc[mi][nf], afr[mi], bfr[nf]);
        }

        if (ch < ND / BK - 1) {
            const int nxt = cur ^ 1;
            As[nxt][ak + 0][am] = __uint_as_float(f2tf32(pa0.x));
            As[nxt][ak + 1][am] = __uint_as_float(f2tf32(pa0.y));
            As[nxt][ak + 2][am] = __uint_as_float(f2tf32(pa0.z));
            As[nxt][ak + 3][am] = __uint_as_float(f2tf32(pa0.w));
            As[nxt][ak + 4][am] = __uint_as_float(f2tf32(pa1.x));
            As[nxt][ak + 5][am] = __uint_as_float(f2tf32(pa1.y));
            As[nxt][ak + 6][am] = __uint_as_float(f2tf32(pa1.z));
            As[nxt][ak + 7][am] = __uint_as_float(f2tf32(pa1.w));
            float4 cb0 = make_float4(__uint_as_float(f2tf32(pb0.x)),
                                     __uint_as_float(f2tf32(pb0.y)),
                                     __uint_as_float(f2tf32(pb0.z)),
                                     __uint_as_float(f2tf32(pb0.w)));
            float4 cb1 = make_float4(__uint_as_float(f2tf32(pb1.x)),
                                     __uint_as_float(f2tf32(pb1.y)),
                                     __uint_as_float(f2tf32(pb1.z)),
                                     __uint_as_float(f2tf32(pb1.w)));
            *(float4*)&Bs[nxt][bkr][bn8]     = cb0;
            *(float4*)&Bs[nxt][bkr][bn8 + 4] = cb1;
            __syncthreads();
        }
    }

    // epilogue: +bias, scatter to [B,H,L,Dh]. Each warp covers 2 heads.
    const int h_base = (ncol0 >> 4) + (warp_n >> 4);
    #pragma unroll
    for (int mi = 0; mi < 4; ++mi) {
        const int r0 = by * 128 + warp_m + mi * 16 + g;
        const int r1 = r0 + 8;
        const int b0 = r0 / NL, l0 = r0 - b0 * NL;
        const int b1 = r1 / NL, l1 = r1 - b1 * NL;
        #pragma unroll
        for (int nf = 0; nf < 4; ++nf) {
            const int h = h_base + (nf >> 1);
            const int d = ((nf & 1) << 3) + 2 * c;      // even -> 8B aligned
            const float bi0 = bias[ncol0 + warp_n + nf * 8 + 2 * c];
            const float bi1 = bias[ncol0 + warp_n + nf * 8 + 2 * c + 1];
            float* p0 = OUT + (((size_t)(b0 * NH + h) * NL + l0) << 4) + d;
            float* p1 = OUT + (((size_t)(b1 * NH + h) * NL + l1) << 4) + d;
            *(float2*)p0 = make_float2(acc[mi][nf][0] + bi0, acc[mi][nf][1] + bi1);
            *(float2*)p1 = make_float2(acc[mi][nf][2] + bi0, acc[mi][nf][3] + bi1);
        }
    }
}

// ---------------- Kernel 2: tensor-core MHA per (b,h) ----------------
// S = Q K^T via mma (tf32), exp (no max: scores bounded, mask -> exact 0),
// P re-laid C-frag -> A-frag through warp-private smem staging, PV via mma.
#define VT_STRIDE 212
#define QK_STRIDE 17
#define PST_STRIDE 10   // EVEN stride: row base stays 8B-aligned for the float2 store

__global__ __launch_bounds__(256)
void attn_kernel(const int* __restrict__ his_mask)
{
    const int h = blockIdx.x;
    const int b = blockIdx.y;
    const int tid  = threadIdx.x;
    const int lane = tid & 31;
    const int wid  = tid >> 5;
    const int g = lane >> 2;     // row within 8
    const int c = lane & 3;      // quad col

    __shared__ float Qs[208][QK_STRIDE];        // tf32 bits, rows 200..207 zeroed
    __shared__ float Ks[200][QK_STRIDE];        // tf32 bits
    __shared__ float Vt[16][VT_STRIDE];         // transposed V, tf32 bits
    __shared__ float am[NL];
    __shared__ float Pst[8][16][PST_STRIDE];    // per-warp P staging (8B-aligned rows)

    const size_t base = (size_t)(b * NH + h) * NL * NDH;

    // loaders: 200 rows x 16, in float4 chunks
    for (int i = tid; i < NL * 4; i += 256) {
        const int row = i >> 2;
        const int d4  = (i & 3) << 2;
        float4 q = *(const float4*)(g_q + base + row * NDH + d4);
        float4 k = *(const float4*)(g_k + base + row * NDH + d4);
        float4 v = *(const float4*)(g_v + base + row * NDH + d4);
        Qs[row][d4 + 0] = __uint_as_float(f2tf32(q.x));
        Qs[row][d4 + 1] = __uint_as_float(f2tf32(q.y));
        Qs[row][d4 + 2] = __uint_as_float(f2tf32(q.z));
        Qs[row][d4 + 3] = __uint_as_float(f2tf32(q.w));
        Ks[row][d4 + 0] = __uint_as_float(f2tf32(k.x));
        Ks[row][d4 + 1] = __uint_as_float(f2tf32(k.y));
        Ks[row][d4 + 2] = __uint_as_float(f2tf32(k.z));
        Ks[row][d4 + 3] = __uint_as_float(f2tf32(k.w));
        Vt[d4 + 0][row] = __uint_as_float(f2tf32(v.x));
        Vt[d4 + 1][row] = __uint_as_float(f2tf32(v.y));
        Vt[d4 + 2][row] = __uint_as_float(f2tf32(v.z));
        Vt[d4 + 3][row] = __uint_as_float(f2tf32(v.w));
    }
    // zero Q pad rows (200..207)
    for (int i = tid; i < 8 * 16; i += 256)
        Qs[200 + (i >> 4)][i & 15] = 0.f;
    for (int i = tid; i < NL; i += 256)
        am[i] = (his_mask[b * NL + i] > 0) ? 0.f : -10000.f;
    __syncthreads();

    // 13 row-tiles of 16, round-robin over 8 warps
    for (int t = wid; t < 13; t += 8) {
        const int r0 = t * 16;

        // Q a-frags (persistent over key loop): 2 k-steps
        uint32_t aq[2][4];
        #pragma unroll
        for (int ks = 0; ks < 2; ++ks) {
            const int kk = ks * 8;
            aq[ks][0] = __float_as_uint(Qs[r0 + g    ][c     + kk]);
            aq[ks][1] = __float_as_uint(Qs[r0 + g + 8][c     + kk]);
            aq[ks][2] = __float_as_uint(Qs[r0 + g    ][c + 4 + kk]);
            aq[ks][3] = __float_as_uint(Qs[r0 + g + 8][c + 4 + kk]);
        }

        float ctx0[4] = {0.f, 0.f, 0.f, 0.f};   // dh 0..7
        float ctx1[4] = {0.f, 0.f, 0.f, 0.f};   // dh 8..15
        float sum_lo = 0.f, sum_hi = 0.f;

        #pragma unroll 1
        for (int kc = 0; kc < NL / 8; ++kc) {
            const int k0 = kc * 8;

            uint32_t bk0[2], bk1[2];
            bk0[0] = __float_as_uint(Ks[k0 + g][c     ]);
            bk0[1] = __float_as_uint(Ks[k0 + g][c + 4 ]);
            bk1[0] = __float_as_uint(Ks[k0 + g][c + 8 ]);
            bk1[1] = __float_as_uint(Ks[k0 + g][c + 12]);

            float s[4] = {0.f, 0.f, 0.f, 0.f};
            mma_tf32(s, aq[0], bk0);
            mma_tf32(s, aq[1], bk1);

            const float a0 = am[k0 + 2 * c];
            const float a1 = am[k0 + 2 * c + 1];
            float p0 = __expf(fmaf(s[0], 0.25f, a0));
            float p1 = __expf(fmaf(s[1], 0.25f, a1));
            float p2 = __expf(fmaf(s[2], 0.25f, a0));
            float p3 = __expf(fmaf(s[3], 0.25f, a1));

            // round P to tf32 ONCE; use same values for numerator and denominator
            const uint32_t t0 = f2tf32(p0), t1 = f2tf32(p1);
            const uint32_t t2 = f2tf32(p2), t3 = f2tf32(p3);
            const float q0 = __uint_as_float(t0), q1 = __uint_as_float(t1);
            const float q2 = __uint_as_float(t2), q3 = __uint_as_float(t3);
            sum_lo += q0 + q1;
            sum_hi += q2 + q3;

            // stage C-frag -> A-frag layout (rows are 40B apart: float2 stays aligned)
            *(float2*)&Pst[wid][g    ][2 * c] = make_float2(q0, q1);
            *(float2*)&Pst[wid][g + 8][2 * c] = make_float2(q2, q3);
            __syncwarp();

            uint32_t ap[4];
            ap[0] = __float_as_uint(Pst[wid][g    ][c    ]);
            ap[1] = __float_as_uint(Pst[wid][g + 8][c    ]);
            ap[2] = __float_as_uint(Pst[wid][g    ][c + 4]);
            ap[3] = __float_as_uint(Pst[wid][g + 8][c + 4]);

            uint32_t bv0[2], bv1[2];
            bv0[0] = __float_as_uint(Vt[g    ][k0 + c    ]);
            bv0[1] = __float_as_uint(Vt[g    ][k0 + c + 4]);
            bv1[0] = __float_as_uint(Vt[g + 8][k0 + c    ]);
            bv1[1] = __float_as_uint(Vt[g + 8][k0 + c + 4]);

            mma_tf32(ctx0, ap, bv0);
            mma_tf32(ctx1, ap, bv1);
            __syncwarp();
        }

        // row sums: reduce across the 4 quad threads
        sum_lo += __shfl_xor_sync(0xffffffffu, sum_lo, 1);
        sum_lo += __shfl_xor_sync(0xffffffffu, sum_lo, 2);
        sum_hi += __shfl_xor_sync(0xffffffffu, sum_hi, 1);
        sum_hi += __shfl_xor_sync(0xffffffffu, sum_hi, 2);
        const float inv_lo = 1.0f / sum_lo;
        const float inv_hi = 1.0f / sum_hi;

        const int row_lo = r0 + g;
        const int row_hi = r0 + g + 8;
        if (row_lo < NL) {
            float* p = g_ctx + ((size_t)b * NL + row_lo) * ND + h * NDH;
            *(float2*)(p + 2 * c)     = make_float2(ctx0[0] * inv_lo, ctx0[1] * inv_lo);
            *(float2*)(p + 8 + 2 * c) = make_float2(ctx1[0] * inv_lo, ctx1[1] * inv_lo);
        }
        if (row_hi < NL) {
            float* p = g_ctx + ((size_t)b * NL + row_hi) * ND + h * NDH;
            *(float2*)(p + 2 * c)     = make_float2(ctx0[2] * inv_hi, ctx0[3] * inv_hi);
            *(float2*)(p + 8 + 2 * c) = make_float2(ctx1[2] * inv_hi, ctx1[3] * inv_hi);
        }
    }
}

// ---------------- Kernel 3a: u = Wo @ query^T  (tiny) ----------------
__global__ __launch_bounds__(256)
void u_kernel(const float* __restrict__ Wo, const float* __restrict__ query)
{
    __shared__ float qs[ND];
    const int tid = threadIdx.x;
    qs[tid] = query[tid];
    __syncthreads();
    const float* row = Wo + (size_t)tid * ND;
    float a0 = 0.f, a1 = 0.f, a2 = 0.f, a3 = 0.f;
    #pragma unroll 8
    for (int n = 0; n < ND; n += 4) {
        a0 = fmaf(row[n + 0], qs[n + 0], a0);
        a1 = fmaf(row[n + 1], qs[n + 1], a1);
        a2 = fmaf(row[n + 2], qs[n + 2], a2);
        a3 = fmaf(row[n + 3], qs[n + 3], a3);
    }
    g_u[tid] = (a0 + a1) + (a2 + a3);
}

// ---------------- Kernel 3b: masked softmax pooling + projected epilogue ----------
__global__ __launch_bounds__(256)
void pool_kernel(const float* __restrict__ Wo, const float* __restrict__ bo,
                 const int* __restrict__ his_mask, float* __restrict__ out)
{
    const int b    = blockIdx.x;
    const int tid  = threadIdx.x;
    const int lane = tid & 31;
    const int warp = tid >> 5;

    __shared__ float ps[NL];
    __shared__ float pooled[ND];
    __shared__ float red[8];

    const float* C = g_ctx + (size_t)b * NL * ND;

    float4 ua = ((const float4*)g_u)[lane * 2];
    float4 ub = ((const float4*)g_u)[lane * 2 + 1];

    for (int l = warp; l < NL; l += 8) {
        const float4* c4 = (const float4*)(C + (size_t)l * ND);
        float4 xa = c4[lane * 2], xb = c4[lane * 2 + 1];
        float acc = xa.x * ua.x + xa.y * ua.y + xa.z * ua.z + xa.w * ua.w
                  + xb.x * ub.x + xb.y * ub.y + xb.z * ub.z + xb.w * ub.w;
        #pragma unroll
        for (int o = 16; o; o >>= 1) acc += __shfl_xor_sync(0xffffffffu, acc, o);
        if (lane == 0)
            ps[l] = (his_mask[b * NL + l] > 0) ? acc * 0.0625f : -1e9f;
    }
    __syncthreads();

    float v = (tid < NL) ? ps[tid] : -3.0e38f;
    float mx = v;
    #pragma unroll
    for (int o = 16; o; o >>= 1) mx = fmaxf(mx, __shfl_xor_sync(0xffffffffu, mx, o));
    if (lane == 0) red[warp] = mx;
    __syncthreads();
    float bm = red[0];
    #pragma unroll
    for (int i = 1; i < 8; ++i) bm = fmaxf(bm, red[i]);

    float e = (tid < NL) ? __expf(v - bm) : 0.f;
    float sv = e;
    #pragma unroll
    for (int o = 16; o; o >>= 1) sv += __shfl_xor_sync(0xffffffffu, sv, o);
    __syncthreads();
    if (lane == 0) red[warp] = sv;
    if (tid < NL) ps[tid] = e;
    __syncthreads();
    float tot = (red[0] + red[1]) + (red[2] + red[3])
              + (red[4] + red[5]) + (red[6] + red[7]);
    float inv = 1.0f / tot;

    {
        float a0 = 0.f, a1 = 0.f, a2 = 0.f, a3 = 0.f;
        const float* Cd = C + tid;
        for (int l = 0; l < NL; l += 4) {
            a0 = fmaf(ps[l + 0], Cd[(size_t)(l + 0) * ND], a0);
            a1 = fmaf(ps[l + 1], Cd[(size_t)(l + 1) * ND], a1);
            a2 = fmaf(ps[l + 2], Cd[(size_t)(l + 2) * ND], a2);
            a3 = fmaf(ps[l + 3], Cd[(size_t)(l + 3) * ND], a3);
        }
        pooled[tid] = ((a0 + a1) + (a2 + a3)) * inv;
    }
    __syncthreads();

    float o = bo[tid];
    const float* Wn = Wo + tid;
    #pragma unroll 8
    for (int d = 0; d < ND; ++d) o = fmaf(pooled[d], Wn[(size_t)d * ND], o);
    out[(size_t)b * ND + tid] = o;
}

// ---------------- launch ----------------
extern "C" void kernel_launch(void* const* d_in, const int* in_sizes, int n_in,
                              void* d_out, int out_size)
{
    const float* news  = (const float*)d_in[0];
    const int*   hmask = (const int*)  d_in[1];
    const float* Wq    = (const float*)d_in[2];
    const float* bq    = (const float*)d_in[3];
    const float* Wk    = (const float*)d_in[4];
    const float* bk    = (const float*)d_in[5];
    const float* Wv    = (const float*)d_in[6];
    const float* bvv   = (const float*)d_in[7];
    const float* Wo    = (const float*)d_in[8];
    const float* bo    = (const float*)d_in[9];
    const float* query = (const float*)d_in[10];
    float* out = (float*)d_out;

    dim3 gemm_grid(6, (NB * NL) / 128);            // 6 x 400
    qkv_mma_kernel<<<gemm_grid, 256>>>(news, Wq, bq, Wk, bk, Wv, bvv);

    dim3 attn_grid(NH, NB);                        // 16 x 256
    attn_kernel<<<attn_grid, 256>>>(hmask);

    u_kernel<<<1, 256>>>(Wo, query);

    pool_kernel<<<NB, 256>>>(Wo, bo, hmask, out);
}